// round 11
// baseline (speedup 1.0000x reference)
#include <cuda_runtime.h>
#include <cuda_bf16.h>
#include <cstdint>
#include <math.h>

// Problem constants
#define BB   2
#define TT   2048
#define DIMC 2048
#define NH   16
#define NHK  2
#define HG   8
#define HD   128
#define MROWS (BB*TT)   // 4096
#define KDIM 2048

// ---------------- scratch (device globals) ----------------------------------
__device__ __nv_bfloat16 g_xh [(size_t)MROWS * KDIM];
__device__ __nv_bfloat16 g_xl [(size_t)MROWS * KDIM];
__device__ __nv_bfloat16 g_qh [(size_t)MROWS * NH  * HD];
__device__ __nv_bfloat16 g_ql [(size_t)MROWS * NH  * HD];
__device__ __nv_bfloat16 g_kh [(size_t)MROWS * NHK * HD];
__device__ __nv_bfloat16 g_kl [(size_t)MROWS * NHK * HD];
__device__ __nv_bfloat16 g_vh [(size_t)MROWS * NHK * HD];
__device__ __nv_bfloat16 g_vl [(size_t)MROWS * NHK * HD];
__device__ __nv_bfloat16 g_oah[(size_t)MROWS * KDIM];
__device__ __nv_bfloat16 g_oal[(size_t)MROWS * KDIM];
__device__ __nv_bfloat16 g_wqh[(size_t)2048 * KDIM];
__device__ __nv_bfloat16 g_wql[(size_t)2048 * KDIM];
__device__ __nv_bfloat16 g_wkh[(size_t)256  * KDIM];
__device__ __nv_bfloat16 g_wkl[(size_t)256  * KDIM];
__device__ __nv_bfloat16 g_wvh[(size_t)256  * KDIM];
__device__ __nv_bfloat16 g_wvl[(size_t)256  * KDIM];
__device__ __nv_bfloat16 g_woh[(size_t)2048 * KDIM];
__device__ __nv_bfloat16 g_wol[(size_t)2048 * KDIM];

// ===================== helpers ==============================================
__device__ __forceinline__ uint32_t smem_u32(const void* p) {
    uint32_t a;
    asm("{ .reg .u64 t; cvta.to.shared.u64 t, %1; cvt.u32.u64 %0, t; }" : "=r"(a) : "l"(p));
    return a;
}
__device__ __forceinline__ void ldm_x4(uint32_t addr, uint32_t& r0, uint32_t& r1,
                                       uint32_t& r2, uint32_t& r3) {
    asm volatile("ldmatrix.sync.aligned.m8n8.x4.shared.b16 {%0,%1,%2,%3}, [%4];"
                 : "=r"(r0), "=r"(r1), "=r"(r2), "=r"(r3) : "r"(addr));
}
__device__ __forceinline__ void ldm_x4_t(uint32_t addr, uint32_t& r0, uint32_t& r1,
                                         uint32_t& r2, uint32_t& r3) {
    asm volatile("ldmatrix.sync.aligned.m8n8.x4.trans.shared.b16 {%0,%1,%2,%3}, [%4];"
                 : "=r"(r0), "=r"(r1), "=r"(r2), "=r"(r3) : "r"(addr));
}
__device__ __forceinline__ void mma16816(float* d, const uint32_t* a, const uint32_t* b) {
    asm volatile("mma.sync.aligned.m16n8k16.row.col.f32.bf16.bf16.f32 "
                 "{%0,%1,%2,%3}, {%4,%5,%6,%7}, {%8,%9}, {%0,%1,%2,%3};"
                 : "+f"(d[0]), "+f"(d[1]), "+f"(d[2]), "+f"(d[3])
                 : "r"(a[0]), "r"(a[1]), "r"(a[2]), "r"(a[3]), "r"(b[0]), "r"(b[1]));
}
// split (x,y) fp32 pair into packed bf16x2 hi + lo
__device__ __forceinline__ void pack_split(float x, float y, uint32_t& h, uint32_t& l) {
    __nv_bfloat16 hx = __float2bfloat16(x), hy = __float2bfloat16(y);
    __nv_bfloat16 lx = __float2bfloat16(x - __bfloat162float(hx));
    __nv_bfloat16 ly = __float2bfloat16(y - __bfloat162float(hy));
    __nv_bfloat162 hp(hx, hy), lp(lx, ly);
    h = *(uint32_t*)&hp; l = *(uint32_t*)&lp;
}

// ===================== preprocessing ========================================
__global__ void split_kernel(const float* __restrict__ x,
                             __nv_bfloat16* __restrict__ h,
                             __nv_bfloat16* __restrict__ l, int n4)
{
    int i = blockIdx.x * blockDim.x + threadIdx.x;
    if (i >= n4) return;
    float4 v = *(const float4*)(x + (size_t)i * 4);
    __nv_bfloat16 h0 = __float2bfloat16(v.x), h1 = __float2bfloat16(v.y);
    __nv_bfloat16 h2 = __float2bfloat16(v.z), h3 = __float2bfloat16(v.w);
    __nv_bfloat16 l0 = __float2bfloat16(v.x - __bfloat162float(h0));
    __nv_bfloat16 l1 = __float2bfloat16(v.y - __bfloat162float(h1));
    __nv_bfloat16 l2 = __float2bfloat16(v.z - __bfloat162float(h2));
    __nv_bfloat16 l3 = __float2bfloat16(v.w - __bfloat162float(h3));
    __nv_bfloat162* hp = (__nv_bfloat162*)(h + (size_t)i * 4);
    __nv_bfloat162* lp = (__nv_bfloat162*)(l + (size_t)i * 4);
    hp[0] = __nv_bfloat162(h0, h1); hp[1] = __nv_bfloat162(h2, h3);
    lp[0] = __nv_bfloat162(l0, l1); lp[1] = __nv_bfloat162(l2, l3);
}

__global__ void transpose_split_kernel(const float* __restrict__ W,
                                       __nv_bfloat16* __restrict__ Th,
                                       __nv_bfloat16* __restrict__ Tl,
                                       int Kd, int Nd)
{
    __shared__ float t[32][33];
    int bx = blockIdx.x * 32;
    int by = blockIdx.y * 32;
    int tx = threadIdx.x, ty = threadIdx.y;
    #pragma unroll
    for (int i = 0; i < 32; i += 8)
        t[ty + i][tx] = W[(size_t)(by + ty + i) * Nd + bx + tx];
    __syncthreads();
    #pragma unroll
    for (int i = 0; i < 32; i += 8) {
        float v = t[tx][ty + i];
        __nv_bfloat16 hv = __float2bfloat16(v);
        __nv_bfloat16 lv = __float2bfloat16(v - __bfloat162float(hv));
        size_t o = (size_t)(bx + ty + i) * Kd + by + tx;
        Th[o] = hv;
        Tl[o] = lv;
    }
}

// ===================== HMMA split-bf16 GEMM =================================
// C = (Ah+Al)[M,K] @ (Bh+Bl)[N,K]^T + bias.
// If Cl != null: write split bf16 (Ch,Cl). Else write fp32 C.
#define GS       72
#define TILE_E   (128 * GS)
#define SA_H     0
#define SA_L     (TILE_E * 2)
#define SB_H     (TILE_E * 4)
#define SB_L     (TILE_E * 6)
#define GEMM_SMEM_BYTES (TILE_E * 8)

__global__ __launch_bounds__(256, 1)
void gemm_mma_kernel(const __nv_bfloat16* __restrict__ Ah,
                     const __nv_bfloat16* __restrict__ Al,
                     const __nv_bfloat16* __restrict__ Bh,
                     const __nv_bfloat16* __restrict__ Bl,
                     const float* __restrict__ bias,
                     float* __restrict__ C,
                     __nv_bfloat16* __restrict__ Ch,
                     __nv_bfloat16* __restrict__ Cl,
                     int M, int N, int K)
{
    extern __shared__ char smem[];
    const uint32_t sb = smem_u32(smem);

    const int tid  = threadIdx.x;
    const int wid  = tid >> 5;
    const int lane = tid & 31;
    const int n0 = blockIdx.x * 128;
    const int m0 = blockIdx.y * 128;
    const int wm = (wid >> 2) * 64;
    const int wn = (wid & 3) * 32;

    float acc[4][4][4];
    #pragma unroll
    for (int i = 0; i < 4; i++)
        #pragma unroll
        for (int j = 0; j < 4; j++)
            #pragma unroll
            for (int q = 0; q < 4; q++) acc[i][j][q] = 0.f;

    const int a_row = wm + (lane & 15);
    const int a_kof = (lane >> 4) * 8;
    const int b_row = wn + (lane & 7) + ((lane >> 4) << 3);
    const int b_kof = ((lane >> 3) & 1) * 8;

    for (int k0 = 0; k0 < K; k0 += 64) {
        #pragma unroll
        for (int i = 0; i < 4; i++) {
            int idx = tid + i * 256;
            int r   = idx >> 3;
            int c8  = idx & 7;
            uint32_t so = (uint32_t)(r * GS + c8 * 8) * 2;
            size_t ga = (size_t)(m0 + r) * K + k0 + c8 * 8;
            size_t gb = (size_t)(n0 + r) * K + k0 + c8 * 8;
            *(uint4*)(smem + SA_H + so) = *(const uint4*)(Ah + ga);
            *(uint4*)(smem + SA_L + so) = *(const uint4*)(Al + ga);
            *(uint4*)(smem + SB_H + so) = *(const uint4*)(Bh + gb);
            *(uint4*)(smem + SB_L + so) = *(const uint4*)(Bl + gb);
        }
        __syncthreads();

        #pragma unroll
        for (int ks = 0; ks < 4; ks++) {
            const int kk = ks * 16;
            uint32_t ah[4][4], al[4][4], bh[4][2], bl[4][2];

            #pragma unroll
            for (int mi = 0; mi < 4; mi++) {
                uint32_t off = (uint32_t)((a_row + mi * 16) * GS + kk + a_kof) * 2;
                ldm_x4(sb + SA_H + off, ah[mi][0], ah[mi][1], ah[mi][2], ah[mi][3]);
                ldm_x4(sb + SA_L + off, al[mi][0], al[mi][1], al[mi][2], al[mi][3]);
            }
            #pragma unroll
            for (int p = 0; p < 2; p++) {
                uint32_t off = (uint32_t)((b_row + p * 16) * GS + kk + b_kof) * 2;
                ldm_x4(sb + SB_H + off, bh[2*p][0], bh[2*p][1], bh[2*p+1][0], bh[2*p+1][1]);
                ldm_x4(sb + SB_L + off, bl[2*p][0], bl[2*p][1], bl[2*p+1][0], bl[2*p+1][1]);
            }
            #pragma unroll
            for (int mi = 0; mi < 4; mi++)
                #pragma unroll
                for (int nj = 0; nj < 4; nj++) {
                    mma16816(acc[mi][nj], ah[mi], bh[nj]);
                    mma16816(acc[mi][nj], ah[mi], bl[nj]);
                    mma16816(acc[mi][nj], al[mi], bh[nj]);
                }
        }
        __syncthreads();
    }

    const int r_base = m0 + wm + (lane >> 2);
    const int c_base = n0 + wn + (lane & 3) * 2;
    #pragma unroll
    for (int mi = 0; mi < 4; mi++) {
        #pragma unroll
        for (int nj = 0; nj < 4; nj++) {
            int cc = c_base + nj * 8;
            float b0 = bias[cc], b1 = bias[cc + 1];
            int r0 = r_base + mi * 16;
            float v00 = acc[mi][nj][0] + b0, v01 = acc[mi][nj][1] + b1;
            float v10 = acc[mi][nj][2] + b0, v11 = acc[mi][nj][3] + b1;
            if (Cl) {
                uint32_t h0, l0, h1, l1;
                pack_split(v00, v01, h0, l0);
                pack_split(v10, v11, h1, l1);
                *(uint32_t*)(Ch + (size_t)r0 * N + cc)       = h0;
                *(uint32_t*)(Cl + (size_t)r0 * N + cc)       = l0;
                *(uint32_t*)(Ch + (size_t)(r0 + 8) * N + cc) = h1;
                *(uint32_t*)(Cl + (size_t)(r0 + 8) * N + cc) = l1;
            } else {
                *(float2*)(C + (size_t)r0 * N + cc)       = make_float2(v00, v01);
                *(float2*)(C + (size_t)(r0 + 8) * N + cc) = make_float2(v10, v11);
            }
        }
    }
}

// ======================= HMMA flash attention ================================
// Block: 128 q-rows of one (b,h); 8 warps x 16 q-rows. kv tiles of 64.
// smem (bf16, stride 136): Qh/Ql 128x136, Kh/Kl/Vh/Vl 64x136.
#define QS 136
#define OQ_H 0
#define OQ_L (128*QS*2)
#define OK_H (OQ_L + 128*QS*2)
#define OK_L (OK_H + 64*QS*2)
#define OV_H (OK_L + 64*QS*2)
#define OV_L (OV_H + 64*QS*2)
#define ATTN_SMEM_BYTES (OV_L + 64*QS*2)   // 139264

__global__ __launch_bounds__(256, 1)
void attn_mma_kernel(const __nv_bfloat16* __restrict__ Qh,
                     const __nv_bfloat16* __restrict__ Ql,
                     const __nv_bfloat16* __restrict__ Kh,
                     const __nv_bfloat16* __restrict__ Kl,
                     const __nv_bfloat16* __restrict__ Vh,
                     const __nv_bfloat16* __restrict__ Vl,
                     __nv_bfloat16* __restrict__ Oah,
                     __nv_bfloat16* __restrict__ Oal)
{
    extern __shared__ char smem[];
    const uint32_t sb = smem_u32(smem);

    const int tid  = threadIdx.x;
    const int wid  = tid >> 5;
    const int lane = tid & 31;
    const int q0 = blockIdx.x * 128;
    const int b  = blockIdx.y >> 4;
    const int h  = blockIdx.y & 15;
    const int hk = h >> 3;
    const int wq = wid * 16;

    // ---- load Q tile (128 x 128, h+l) ----
    for (int idx = tid; idx < 128 * 16; idx += 256) {
        int r  = idx >> 4;
        int c8 = idx & 15;
        uint32_t so = (uint32_t)(r * QS + c8 * 8) * 2;
        size_t g = (((size_t)(b*TT + q0 + r) * NH) + h) * HD + c8 * 8;
        *(uint4*)(smem + OQ_H + so) = *(const uint4*)(Qh + g);
        *(uint4*)(smem + OQ_L + so) = *(const uint4*)(Ql + g);
    }

    const int a_row  = wq + (lane & 15);
    const int a_kof  = (lane >> 4) * 8;
    const int kb_row = (lane & 7) + ((lane >> 4) << 3);
    const int kb_kof = ((lane >> 3) & 1) * 8;
    const int v_row  = lane & 15;
    const int v_col  = (lane >> 4) * 8;

    float accO[16][4];
    #pragma unroll
    for (int i = 0; i < 16; i++)
        #pragma unroll
        for (int q = 0; q < 4; q++) accO[i][q] = 0.f;
    float m0r = -1e30f, m1r = -1e30f, l0r = 0.f, l1r = 0.f;
    const float scale = 0.08838834764831845f;

    for (int j0 = 0; j0 < TT; j0 += 64) {
        __syncthreads();   // previous-iter smem reads done (also covers Q store, 1st iter)
        // ---- load K,V tile (64 x 128, h+l each) ----
        for (int idx = tid; idx < 64 * 16; idx += 256) {
            int r  = idx >> 4;
            int c8 = idx & 15;
            uint32_t so = (uint32_t)(r * QS + c8 * 8) * 2;
            size_t g = (((size_t)(b*TT + j0 + r) * NHK) + hk) * HD + c8 * 8;
            *(uint4*)(smem + OK_H + so) = *(const uint4*)(Kh + g);
            *(uint4*)(smem + OK_L + so) = *(const uint4*)(Kl + g);
            *(uint4*)(smem + OV_H + so) = *(const uint4*)(Vh + g);
            *(uint4*)(smem + OV_L + so) = *(const uint4*)(Vl + g);
        }
        __syncthreads();

        // ---- S = Q K^T (3 split terms) ----
        float s[8][4];
        #pragma unroll
        for (int t = 0; t < 8; t++)
            #pragma unroll
            for (int q = 0; q < 4; q++) s[t][q] = 0.f;

        #pragma unroll
        for (int ks = 0; ks < 8; ks++) {
            const int kk = ks * 16;
            uint32_t qfh[4], qfl[4];
            uint32_t qoff = (uint32_t)(a_row * QS + kk + a_kof) * 2;
            ldm_x4(sb + OQ_H + qoff, qfh[0], qfh[1], qfh[2], qfh[3]);
            ldm_x4(sb + OQ_L + qoff, qfl[0], qfl[1], qfl[2], qfl[3]);
            #pragma unroll
            for (int g = 0; g < 4; g++) {
                uint32_t koff = (uint32_t)((g*16 + kb_row) * QS + kk + kb_kof) * 2;
                uint32_t h0,h1,h2,h3, e0,e1,e2,e3;
                ldm_x4(sb + OK_H + koff, h0, h1, h2, h3);
                ldm_x4(sb + OK_L + koff, e0, e1, e2, e3);
                uint32_t bh0[2] = {h0, h1}, bh1[2] = {h2, h3};
                uint32_t bl0[2] = {e0, e1}, bl1[2] = {e2, e3};
                mma16816(s[2*g],   qfh, bh0);
                mma16816(s[2*g],   qfh, bl0);
                mma16816(s[2*g],   qfl, bh0);
                mma16816(s[2*g+1], qfh, bh1);
                mma16816(s[2*g+1], qfh, bl1);
                mma16816(s[2*g+1], qfl, bh1);
            }
        }

        // ---- online softmax (rows: lane>>2 and +8) ----
        float ml0 = -1e30f, ml1 = -1e30f;
        #pragma unroll
        for (int t = 0; t < 8; t++) {
            #pragma unroll
            for (int q = 0; q < 4; q++) {
                float sv = fminf(fmaxf(s[t][q] * scale, -100.f), 100.f);
                s[t][q] = sv;
                if (q < 2) ml0 = fmaxf(ml0, sv); else ml1 = fmaxf(ml1, sv);
            }
        }
        ml0 = fmaxf(ml0, __shfl_xor_sync(0xffffffffu, ml0, 1));
        ml0 = fmaxf(ml0, __shfl_xor_sync(0xffffffffu, ml0, 2));
        ml1 = fmaxf(ml1, __shfl_xor_sync(0xffffffffu, ml1, 1));
        ml1 = fmaxf(ml1, __shfl_xor_sync(0xffffffffu, ml1, 2));
        float mn0 = fmaxf(m0r, ml0), mn1 = fmaxf(m1r, ml1);
        float c0 = __expf(m0r - mn0), c1 = __expf(m1r - mn1);
        float ls0 = 0.f, ls1 = 0.f;
        #pragma unroll
        for (int t = 0; t < 8; t++) {
            float p0 = __expf(s[t][0] - mn0);
            float p1 = __expf(s[t][1] - mn0);
            float p2 = __expf(s[t][2] - mn1);
            float p3 = __expf(s[t][3] - mn1);
            s[t][0] = p0; s[t][1] = p1; s[t][2] = p2; s[t][3] = p3;
            ls0 += p0 + p1; ls1 += p2 + p3;
        }
        ls0 += __shfl_xor_sync(0xffffffffu, ls0, 1);
        ls0 += __shfl_xor_sync(0xffffffffu, ls0, 2);
        ls1 += __shfl_xor_sync(0xffffffffu, ls1, 1);
        ls1 += __shfl_xor_sync(0xffffffffu, ls1, 2);
        l0r = l0r * c0 + ls0; m0r = mn0;
        l1r = l1r * c1 + ls1; m1r = mn1;
        #pragma unroll
        for (int nt = 0; nt < 16; nt++) {
            accO[nt][0] *= c0; accO[nt][1] *= c0;
            accO[nt][2] *= c1; accO[nt][3] *= c1;
        }

        // ---- pack P into split A-fragments (in-register) ----
        uint32_t pah[4][4], pal[4][4];
        #pragma unroll
        for (int kt = 0; kt < 4; kt++) {
            int t0 = 2*kt, t1 = t0 + 1;
            pack_split(s[t0][0], s[t0][1], pah[kt][0], pal[kt][0]);
            pack_split(s[t0][2], s[t0][3], pah[kt][1], pal[kt][1]);
            pack_split(s[t1][0], s[t1][1], pah[kt][2], pal[kt][2]);
            pack_split(s[t1][2], s[t1][3], pah[kt][3], pal[kt][3]);
        }

        // ---- O += P V (3 split terms) ----
        #pragma unroll
        for (int kt = 0; kt < 4; kt++) {
            #pragma unroll
            for (int g = 0; g < 8; g++) {
                uint32_t voff = (uint32_t)((kt*16 + v_row) * QS + g*16 + v_col) * 2;
                uint32_t h0,h1,h2,h3, e0,e1,e2,e3;
                ldm_x4_t(sb + OV_H + voff, h0, h1, h2, h3);
                ldm_x4_t(sb + OV_L + voff, e0, e1, e2, e3);
                uint32_t bh0[2] = {h0, h1}, bh1[2] = {h2, h3};
                uint32_t bl0[2] = {e0, e1}, bl1[2] = {e2, e3};
                mma16816(accO[2*g],   pah[kt], bh0);
                mma16816(accO[2*g],   pah[kt], bl0);
                mma16816(accO[2*g],   pal[kt], bh0);
                mma16816(accO[2*g+1], pah[kt], bh1);
                mma16816(accO[2*g+1], pah[kt], bl1);
                mma16816(accO[2*g+1], pal[kt], bh1);
            }
        }
    }

    // ---- epilogue: normalize, split-write Oa [B,T,H,D] as bf16 h/l ----
    float inv0 = 1.0f / l0r, inv1 = 1.0f / l1r;
    int gr0 = q0 + wq + (lane >> 2);
    #pragma unroll
    for (int nt = 0; nt < 16; nt++) {
        int d = nt * 8 + (lane & 3) * 2;
        uint32_t h0, e0, h1, e1;
        pack_split(accO[nt][0] * inv0, accO[nt][1] * inv0, h0, e0);
        pack_split(accO[nt][2] * inv1, accO[nt][3] * inv1, h1, e1);
        size_t o0 = (((size_t)(b*TT + gr0)     * NH) + h) * HD + d;
        size_t o1 = (((size_t)(b*TT + gr0 + 8) * NH) + h) * HD + d;
        *(uint32_t*)(Oah + o0) = h0;
        *(uint32_t*)(Oal + o0) = e0;
        *(uint32_t*)(Oah + o1) = h1;
        *(uint32_t*)(Oal + o1) = e1;
    }
}

// ============================ launch ========================================
extern "C" void kernel_launch(void* const* d_in, const int* in_sizes, int n_in,
                              void* d_out, int out_size)
{
    const float* x  = (const float*)d_in[0];
    const float* Wq = (const float*)d_in[1];
    const float* bq = (const float*)d_in[2];
    const float* Wk = (const float*)d_in[3];
    const float* bk = (const float*)d_in[4];
    const float* Wv = (const float*)d_in[5];
    const float* bv = (const float*)d_in[6];
    const float* Wo = (const float*)d_in[7];
    const float* bo = (const float*)d_in[8];
    float* out = (float*)d_out;

    __nv_bfloat16 *xh, *xl, *qh, *ql, *kh, *kl, *vh, *vl, *oah, *oal;
    __nv_bfloat16 *wqh, *wql, *wkh, *wkl, *wvh, *wvl, *woh, *wol;
    cudaGetSymbolAddress((void**)&xh,  g_xh);  cudaGetSymbolAddress((void**)&xl,  g_xl);
    cudaGetSymbolAddress((void**)&qh,  g_qh);  cudaGetSymbolAddress((void**)&ql,  g_ql);
    cudaGetSymbolAddress((void**)&kh,  g_kh);  cudaGetSymbolAddress((void**)&kl,  g_kl);
    cudaGetSymbolAddress((void**)&vh,  g_vh);  cudaGetSymbolAddress((void**)&vl,  g_vl);
    cudaGetSymbolAddress((void**)&oah, g_oah); cudaGetSymbolAddress((void**)&oal, g_oal);
    cudaGetSymbolAddress((void**)&wqh, g_wqh); cudaGetSymbolAddress((void**)&wql, g_wql);
    cudaGetSymbolAddress((void**)&wkh, g_wkh); cudaGetSymbolAddress((void**)&wkl, g_wkl);
    cudaGetSymbolAddress((void**)&wvh, g_wvh); cudaGetSymbolAddress((void**)&wvl, g_wvl);
    cudaGetSymbolAddress((void**)&woh, g_woh); cudaGetSymbolAddress((void**)&wol, g_wol);

    cudaFuncSetAttribute(gemm_mma_kernel, cudaFuncAttributeMaxDynamicSharedMemorySize,
                         GEMM_SMEM_BYTES);
    cudaFuncSetAttribute(attn_mma_kernel, cudaFuncAttributeMaxDynamicSharedMemorySize,
                         ATTN_SMEM_BYTES);

    // 1) split x
    {
        int n4 = (MROWS * KDIM) / 4;
        split_kernel<<<(n4 + 255) / 256, 256>>>(x, xh, xl, n4);
    }
    // 2) transpose + split weights: W[K][N] -> [N][K]
    transpose_split_kernel<<<dim3(2048/32, KDIM/32), dim3(32, 8)>>>(Wq, wqh, wql, KDIM, 2048);
    transpose_split_kernel<<<dim3(256/32,  KDIM/32), dim3(32, 8)>>>(Wk, wkh, wkl, KDIM, 256);
    transpose_split_kernel<<<dim3(256/32,  KDIM/32), dim3(32, 8)>>>(Wv, wvh, wvl, KDIM, 256);
    transpose_split_kernel<<<dim3(2048/32, KDIM/32), dim3(32, 8)>>>(Wo, woh, wol, KDIM, 2048);

    // 3) projections on HMMA; epilogue writes split bf16 directly
    gemm_mma_kernel<<<dim3(2048/128, MROWS/128), 256, GEMM_SMEM_BYTES>>>(
        xh, xl, wqh, wql, bq, nullptr, qh, ql, MROWS, 2048, KDIM);
    gemm_mma_kernel<<<dim3(256/128,  MROWS/128), 256, GEMM_SMEM_BYTES>>>(
        xh, xl, wkh, wkl, bk, nullptr, kh, kl, MROWS, 256, KDIM);
    gemm_mma_kernel<<<dim3(256/128,  MROWS/128), 256, GEMM_SMEM_BYTES>>>(
        xh, xl, wvh, wvl, bv, nullptr, vh, vl, MROWS, 256, KDIM);

    // 4) attention on HMMA; epilogue writes split bf16 directly
    attn_mma_kernel<<<dim3(TT/128, BB*NH), 256, ATTN_SMEM_BYTES>>>(
        qh, ql, kh, kl, vh, vl, oah, oal);

    // 5) output projection -> fp32 out
    gemm_mma_kernel<<<dim3(2048/128, MROWS/128), 256, GEMM_SMEM_BYTES>>>(
        oah, oal, woh, wol, bo, out, nullptr, nullptr, MROWS, 2048, KDIM);
}

// round 12
// speedup vs baseline: 1.0123x; 1.0123x over previous
#include <cuda_runtime.h>
#include <cuda_bf16.h>
#include <cstdint>
#include <math.h>

// Problem constants
#define BB   2
#define TT   2048
#define DIMC 2048
#define NH   16
#define NHK  2
#define HG   8
#define HD   128
#define MROWS (BB*TT)   // 4096
#define KDIM 2048

// ---------------- scratch (device globals) ----------------------------------
__device__ __nv_bfloat16 g_xh [(size_t)MROWS * KDIM];
__device__ __nv_bfloat16 g_xl [(size_t)MROWS * KDIM];
__device__ __nv_bfloat16 g_qh [(size_t)MROWS * NH  * HD];
__device__ __nv_bfloat16 g_ql [(size_t)MROWS * NH  * HD];
__device__ __nv_bfloat16 g_kh [(size_t)MROWS * NHK * HD];
__device__ __nv_bfloat16 g_kl [(size_t)MROWS * NHK * HD];
__device__ __nv_bfloat16 g_vh [(size_t)MROWS * NHK * HD];
__device__ __nv_bfloat16 g_vl [(size_t)MROWS * NHK * HD];
__device__ __nv_bfloat16 g_oah[(size_t)MROWS * KDIM];
__device__ __nv_bfloat16 g_oal[(size_t)MROWS * KDIM];
__device__ __nv_bfloat16 g_wqh[(size_t)2048 * KDIM];
__device__ __nv_bfloat16 g_wql[(size_t)2048 * KDIM];
__device__ __nv_bfloat16 g_wkh[(size_t)256  * KDIM];
__device__ __nv_bfloat16 g_wkl[(size_t)256  * KDIM];
__device__ __nv_bfloat16 g_wvh[(size_t)256  * KDIM];
__device__ __nv_bfloat16 g_wvl[(size_t)256  * KDIM];
__device__ __nv_bfloat16 g_woh[(size_t)2048 * KDIM];
__device__ __nv_bfloat16 g_wol[(size_t)2048 * KDIM];

// ===================== helpers ==============================================
__device__ __forceinline__ uint32_t smem_u32(const void* p) {
    uint32_t a;
    asm("{ .reg .u64 t; cvta.to.shared.u64 t, %1; cvt.u32.u64 %0, t; }" : "=r"(a) : "l"(p));
    return a;
}
__device__ __forceinline__ void ldm_x4(uint32_t addr, uint32_t& r0, uint32_t& r1,
                                       uint32_t& r2, uint32_t& r3) {
    asm volatile("ldmatrix.sync.aligned.m8n8.x4.shared.b16 {%0,%1,%2,%3}, [%4];"
                 : "=r"(r0), "=r"(r1), "=r"(r2), "=r"(r3) : "r"(addr));
}
__device__ __forceinline__ void ldm_x4_t(uint32_t addr, uint32_t& r0, uint32_t& r1,
                                         uint32_t& r2, uint32_t& r3) {
    asm volatile("ldmatrix.sync.aligned.m8n8.x4.trans.shared.b16 {%0,%1,%2,%3}, [%4];"
                 : "=r"(r0), "=r"(r1), "=r"(r2), "=r"(r3) : "r"(addr));
}
__device__ __forceinline__ void mma16816(float* d, const uint32_t* a, const uint32_t* b) {
    asm volatile("mma.sync.aligned.m16n8k16.row.col.f32.bf16.bf16.f32 "
                 "{%0,%1,%2,%3}, {%4,%5,%6,%7}, {%8,%9}, {%0,%1,%2,%3};"
                 : "+f"(d[0]), "+f"(d[1]), "+f"(d[2]), "+f"(d[3])
                 : "r"(a[0]), "r"(a[1]), "r"(a[2]), "r"(a[3]), "r"(b[0]), "r"(b[1]));
}
// split (x,y) fp32 pair into packed bf16x2 hi + lo
__device__ __forceinline__ void pack_split(float x, float y, uint32_t& h, uint32_t& l) {
    __nv_bfloat16 hx = __float2bfloat16(x), hy = __float2bfloat16(y);
    __nv_bfloat16 lx = __float2bfloat16(x - __bfloat162float(hx));
    __nv_bfloat16 ly = __float2bfloat16(y - __bfloat162float(hy));
    __nv_bfloat162 hp(hx, hy), lp(lx, ly);
    h = *(uint32_t*)&hp; l = *(uint32_t*)&lp;
}

// ===================== preprocessing ========================================
__global__ void split_kernel(const float* __restrict__ x,
                             __nv_bfloat16* __restrict__ h,
                             __nv_bfloat16* __restrict__ l, int n4)
{
    int i = blockIdx.x * blockDim.x + threadIdx.x;
    if (i >= n4) return;
    float4 v = *(const float4*)(x + (size_t)i * 4);
    __nv_bfloat16 h0 = __float2bfloat16(v.x), h1 = __float2bfloat16(v.y);
    __nv_bfloat16 h2 = __float2bfloat16(v.z), h3 = __float2bfloat16(v.w);
    __nv_bfloat16 l0 = __float2bfloat16(v.x - __bfloat162float(h0));
    __nv_bfloat16 l1 = __float2bfloat16(v.y - __bfloat162float(h1));
    __nv_bfloat16 l2 = __float2bfloat16(v.z - __bfloat162float(h2));
    __nv_bfloat16 l3 = __float2bfloat16(v.w - __bfloat162float(h3));
    __nv_bfloat162* hp = (__nv_bfloat162*)(h + (size_t)i * 4);
    __nv_bfloat162* lp = (__nv_bfloat162*)(l + (size_t)i * 4);
    hp[0] = __nv_bfloat162(h0, h1); hp[1] = __nv_bfloat162(h2, h3);
    lp[0] = __nv_bfloat162(l0, l1); lp[1] = __nv_bfloat162(l2, l3);
}

__global__ void transpose_split_kernel(const float* __restrict__ W,
                                       __nv_bfloat16* __restrict__ Th,
                                       __nv_bfloat16* __restrict__ Tl,
                                       int Kd, int Nd)
{
    __shared__ float t[32][33];
    int bx = blockIdx.x * 32;
    int by = blockIdx.y * 32;
    int tx = threadIdx.x, ty = threadIdx.y;
    #pragma unroll
    for (int i = 0; i < 32; i += 8)
        t[ty + i][tx] = W[(size_t)(by + ty + i) * Nd + bx + tx];
    __syncthreads();
    #pragma unroll
    for (int i = 0; i < 32; i += 8) {
        float v = t[tx][ty + i];
        __nv_bfloat16 hv = __float2bfloat16(v);
        __nv_bfloat16 lv = __float2bfloat16(v - __bfloat162float(hv));
        size_t o = (size_t)(bx + ty + i) * Kd + by + tx;
        Th[o] = hv;
        Tl[o] = lv;
    }
}

// ===================== HMMA split-bf16 GEMM =================================
// C = (Ah+Al)[M,K] @ (Bh+Bl)[N,K]^T + bias.
// If Cl != null: write split bf16 (Ch,Cl). Else write fp32 C.
#define GS       72
#define TILE_E   (128 * GS)
#define SA_H     0
#define SA_L     (TILE_E * 2)
#define SB_H     (TILE_E * 4)
#define SB_L     (TILE_E * 6)
#define GEMM_SMEM_BYTES (TILE_E * 8)

__global__ __launch_bounds__(256, 1)
void gemm_mma_kernel(const __nv_bfloat16* __restrict__ Ah,
                     const __nv_bfloat16* __restrict__ Al,
                     const __nv_bfloat16* __restrict__ Bh,
                     const __nv_bfloat16* __restrict__ Bl,
                     const float* __restrict__ bias,
                     float* __restrict__ C,
                     __nv_bfloat16* __restrict__ Ch,
                     __nv_bfloat16* __restrict__ Cl,
                     int M, int N, int K)
{
    extern __shared__ char smem[];
    const uint32_t sb = smem_u32(smem);

    const int tid  = threadIdx.x;
    const int wid  = tid >> 5;
    const int lane = tid & 31;
    const int n0 = blockIdx.x * 128;
    const int m0 = blockIdx.y * 128;
    const int wm = (wid >> 2) * 64;
    const int wn = (wid & 3) * 32;

    float acc[4][4][4];
    #pragma unroll
    for (int i = 0; i < 4; i++)
        #pragma unroll
        for (int j = 0; j < 4; j++)
            #pragma unroll
            for (int q = 0; q < 4; q++) acc[i][j][q] = 0.f;

    const int a_row = wm + (lane & 15);
    const int a_kof = (lane >> 4) * 8;
    const int b_row = wn + (lane & 7) + ((lane >> 4) << 3);
    const int b_kof = ((lane >> 3) & 1) * 8;

    for (int k0 = 0; k0 < K; k0 += 64) {
        #pragma unroll
        for (int i = 0; i < 4; i++) {
            int idx = tid + i * 256;
            int r   = idx >> 3;
            int c8  = idx & 7;
            uint32_t so = (uint32_t)(r * GS + c8 * 8) * 2;
            size_t ga = (size_t)(m0 + r) * K + k0 + c8 * 8;
            size_t gb = (size_t)(n0 + r) * K + k0 + c8 * 8;
            *(uint4*)(smem + SA_H + so) = *(const uint4*)(Ah + ga);
            *(uint4*)(smem + SA_L + so) = *(const uint4*)(Al + ga);
            *(uint4*)(smem + SB_H + so) = *(const uint4*)(Bh + gb);
            *(uint4*)(smem + SB_L + so) = *(const uint4*)(Bl + gb);
        }
        __syncthreads();

        #pragma unroll
        for (int ks = 0; ks < 4; ks++) {
            const int kk = ks * 16;
            uint32_t ah[4][4], al[4][4], bh[4][2], bl[4][2];

            #pragma unroll
            for (int mi = 0; mi < 4; mi++) {
                uint32_t off = (uint32_t)((a_row + mi * 16) * GS + kk + a_kof) * 2;
                ldm_x4(sb + SA_H + off, ah[mi][0], ah[mi][1], ah[mi][2], ah[mi][3]);
                ldm_x4(sb + SA_L + off, al[mi][0], al[mi][1], al[mi][2], al[mi][3]);
            }
            #pragma unroll
            for (int p = 0; p < 2; p++) {
                uint32_t off = (uint32_t)((b_row + p * 16) * GS + kk + b_kof) * 2;
                ldm_x4(sb + SB_H + off, bh[2*p][0], bh[2*p][1], bh[2*p+1][0], bh[2*p+1][1]);
                ldm_x4(sb + SB_L + off, bl[2*p][0], bl[2*p][1], bl[2*p+1][0], bl[2*p+1][1]);
            }
            #pragma unroll
            for (int mi = 0; mi < 4; mi++)
                #pragma unroll
                for (int nj = 0; nj < 4; nj++) {
                    mma16816(acc[mi][nj], ah[mi], bh[nj]);
                    mma16816(acc[mi][nj], ah[mi], bl[nj]);
                    mma16816(acc[mi][nj], al[mi], bh[nj]);
                }
        }
        __syncthreads();
    }

    const int r_base = m0 + wm + (lane >> 2);
    const int c_base = n0 + wn + (lane & 3) * 2;
    #pragma unroll
    for (int mi = 0; mi < 4; mi++) {
        #pragma unroll
        for (int nj = 0; nj < 4; nj++) {
            int cc = c_base + nj * 8;
            float b0 = bias[cc], b1 = bias[cc + 1];
            int r0 = r_base + mi * 16;
            float v00 = acc[mi][nj][0] + b0, v01 = acc[mi][nj][1] + b1;
            float v10 = acc[mi][nj][2] + b0, v11 = acc[mi][nj][3] + b1;
            if (Cl) {
                uint32_t h0, l0, h1, l1;
                pack_split(v00, v01, h0, l0);
                pack_split(v10, v11, h1, l1);
                *(uint32_t*)(Ch + (size_t)r0 * N + cc)       = h0;
                *(uint32_t*)(Cl + (size_t)r0 * N + cc)       = l0;
                *(uint32_t*)(Ch + (size_t)(r0 + 8) * N + cc) = h1;
                *(uint32_t*)(Cl + (size_t)(r0 + 8) * N + cc) = l1;
            } else {
                *(float2*)(C + (size_t)r0 * N + cc)       = make_float2(v00, v01);
                *(float2*)(C + (size_t)(r0 + 8) * N + cc) = make_float2(v10, v11);
            }
        }
    }
}

// ======================= HMMA flash attention ================================
// Block: 128 q-rows of one (b,h); 8 warps x 16 q-rows. kv tiles of 64.
// smem (bf16, stride 136): Qh/Ql 128x136, Kh/Kl/Vh/Vl 64x136.
#define QS 136
#define OQ_H 0
#define OQ_L (128*QS*2)
#define OK_H (OQ_L + 128*QS*2)
#define OK_L (OK_H + 64*QS*2)
#define OV_H (OK_L + 64*QS*2)
#define OV_L (OV_H + 64*QS*2)
#define ATTN_SMEM_BYTES (OV_L + 64*QS*2)   // 139264

__global__ __launch_bounds__(256, 1)
void attn_mma_kernel(const __nv_bfloat16* __restrict__ Qh,
                     const __nv_bfloat16* __restrict__ Ql,
                     const __nv_bfloat16* __restrict__ Kh,
                     const __nv_bfloat16* __restrict__ Kl,
                     const __nv_bfloat16* __restrict__ Vh,
                     const __nv_bfloat16* __restrict__ Vl,
                     __nv_bfloat16* __restrict__ Oah,
                     __nv_bfloat16* __restrict__ Oal)
{
    extern __shared__ char smem[];
    const uint32_t sb = smem_u32(smem);

    const int tid  = threadIdx.x;
    const int wid  = tid >> 5;
    const int lane = tid & 31;
    const int q0 = blockIdx.x * 128;
    const int b  = blockIdx.y >> 4;
    const int h  = blockIdx.y & 15;
    const int hk = h >> 3;
    const int wq = wid * 16;

    // ---- load Q tile (128 x 128, h+l) ----
    for (int idx = tid; idx < 128 * 16; idx += 256) {
        int r  = idx >> 4;
        int c8 = idx & 15;
        uint32_t so = (uint32_t)(r * QS + c8 * 8) * 2;
        size_t g = (((size_t)(b*TT + q0 + r) * NH) + h) * HD + c8 * 8;
        *(uint4*)(smem + OQ_H + so) = *(const uint4*)(Qh + g);
        *(uint4*)(smem + OQ_L + so) = *(const uint4*)(Ql + g);
    }

    const int a_row  = wq + (lane & 15);
    const int a_kof  = (lane >> 4) * 8;
    const int kb_row = (lane & 7) + ((lane >> 4) << 3);
    const int kb_kof = ((lane >> 3) & 1) * 8;
    const int v_row  = lane & 15;
    const int v_col  = (lane >> 4) * 8;

    float accO[16][4];
    #pragma unroll
    for (int i = 0; i < 16; i++)
        #pragma unroll
        for (int q = 0; q < 4; q++) accO[i][q] = 0.f;
    float m0r = -1e30f, m1r = -1e30f, l0r = 0.f, l1r = 0.f;
    const float scale = 0.08838834764831845f;

    for (int j0 = 0; j0 < TT; j0 += 64) {
        __syncthreads();   // previous-iter smem reads done (also covers Q store, 1st iter)
        // ---- load K,V tile (64 x 128, h+l each) ----
        for (int idx = tid; idx < 64 * 16; idx += 256) {
            int r  = idx >> 4;
            int c8 = idx & 15;
            uint32_t so = (uint32_t)(r * QS + c8 * 8) * 2;
            size_t g = (((size_t)(b*TT + j0 + r) * NHK) + hk) * HD + c8 * 8;
            *(uint4*)(smem + OK_H + so) = *(const uint4*)(Kh + g);
            *(uint4*)(smem + OK_L + so) = *(const uint4*)(Kl + g);
            *(uint4*)(smem + OV_H + so) = *(const uint4*)(Vh + g);
            *(uint4*)(smem + OV_L + so) = *(const uint4*)(Vl + g);
        }
        __syncthreads();

        // ---- S = Q K^T (3 split terms) ----
        float s[8][4];
        #pragma unroll
        for (int t = 0; t < 8; t++)
            #pragma unroll
            for (int q = 0; q < 4; q++) s[t][q] = 0.f;

        #pragma unroll
        for (int ks = 0; ks < 8; ks++) {
            const int kk = ks * 16;
            uint32_t qfh[4], qfl[4];
            uint32_t qoff = (uint32_t)(a_row * QS + kk + a_kof) * 2;
            ldm_x4(sb + OQ_H + qoff, qfh[0], qfh[1], qfh[2], qfh[3]);
            ldm_x4(sb + OQ_L + qoff, qfl[0], qfl[1], qfl[2], qfl[3]);
            #pragma unroll
            for (int g = 0; g < 4; g++) {
                uint32_t koff = (uint32_t)((g*16 + kb_row) * QS + kk + kb_kof) * 2;
                uint32_t h0,h1,h2,h3, e0,e1,e2,e3;
                ldm_x4(sb + OK_H + koff, h0, h1, h2, h3);
                ldm_x4(sb + OK_L + koff, e0, e1, e2, e3);
                uint32_t bh0[2] = {h0, h1}, bh1[2] = {h2, h3};
                uint32_t bl0[2] = {e0, e1}, bl1[2] = {e2, e3};
                mma16816(s[2*g],   qfh, bh0);
                mma16816(s[2*g],   qfh, bl0);
                mma16816(s[2*g],   qfl, bh0);
                mma16816(s[2*g+1], qfh, bh1);
                mma16816(s[2*g+1], qfh, bl1);
                mma16816(s[2*g+1], qfl, bh1);
            }
        }

        // ---- online softmax (rows: lane>>2 and +8) ----
        float ml0 = -1e30f, ml1 = -1e30f;
        #pragma unroll
        for (int t = 0; t < 8; t++) {
            #pragma unroll
            for (int q = 0; q < 4; q++) {
                float sv = fminf(fmaxf(s[t][q] * scale, -100.f), 100.f);
                s[t][q] = sv;
                if (q < 2) ml0 = fmaxf(ml0, sv); else ml1 = fmaxf(ml1, sv);
            }
        }
        ml0 = fmaxf(ml0, __shfl_xor_sync(0xffffffffu, ml0, 1));
        ml0 = fmaxf(ml0, __shfl_xor_sync(0xffffffffu, ml0, 2));
        ml1 = fmaxf(ml1, __shfl_xor_sync(0xffffffffu, ml1, 1));
        ml1 = fmaxf(ml1, __shfl_xor_sync(0xffffffffu, ml1, 2));
        float mn0 = fmaxf(m0r, ml0), mn1 = fmaxf(m1r, ml1);
        float c0 = __expf(m0r - mn0), c1 = __expf(m1r - mn1);
        float ls0 = 0.f, ls1 = 0.f;
        #pragma unroll
        for (int t = 0; t < 8; t++) {
            float p0 = __expf(s[t][0] - mn0);
            float p1 = __expf(s[t][1] - mn0);
            float p2 = __expf(s[t][2] - mn1);
            float p3 = __expf(s[t][3] - mn1);
            s[t][0] = p0; s[t][1] = p1; s[t][2] = p2; s[t][3] = p3;
            ls0 += p0 + p1; ls1 += p2 + p3;
        }
        ls0 += __shfl_xor_sync(0xffffffffu, ls0, 1);
        ls0 += __shfl_xor_sync(0xffffffffu, ls0, 2);
        ls1 += __shfl_xor_sync(0xffffffffu, ls1, 1);
        ls1 += __shfl_xor_sync(0xffffffffu, ls1, 2);
        l0r = l0r * c0 + ls0; m0r = mn0;
        l1r = l1r * c1 + ls1; m1r = mn1;
        #pragma unroll
        for (int nt = 0; nt < 16; nt++) {
            accO[nt][0] *= c0; accO[nt][1] *= c0;
            accO[nt][2] *= c1; accO[nt][3] *= c1;
        }

        // ---- pack P into split A-fragments (in-register) ----
        uint32_t pah[4][4], pal[4][4];
        #pragma unroll
        for (int kt = 0; kt < 4; kt++) {
            int t0 = 2*kt, t1 = t0 + 1;
            pack_split(s[t0][0], s[t0][1], pah[kt][0], pal[kt][0]);
            pack_split(s[t0][2], s[t0][3], pah[kt][1], pal[kt][1]);
            pack_split(s[t1][0], s[t1][1], pah[kt][2], pal[kt][2]);
            pack_split(s[t1][2], s[t1][3], pah[kt][3], pal[kt][3]);
        }

        // ---- O += P V (3 split terms) ----
        #pragma unroll
        for (int kt = 0; kt < 4; kt++) {
            #pragma unroll
            for (int g = 0; g < 8; g++) {
                uint32_t voff = (uint32_t)((kt*16 + v_row) * QS + g*16 + v_col) * 2;
                uint32_t h0,h1,h2,h3, e0,e1,e2,e3;
                ldm_x4_t(sb + OV_H + voff, h0, h1, h2, h3);
                ldm_x4_t(sb + OV_L + voff, e0, e1, e2, e3);
                uint32_t bh0[2] = {h0, h1}, bh1[2] = {h2, h3};
                uint32_t bl0[2] = {e0, e1}, bl1[2] = {e2, e3};
                mma16816(accO[2*g],   pah[kt], bh0);
                mma16816(accO[2*g],   pah[kt], bl0);
                mma16816(accO[2*g],   pal[kt], bh0);
                mma16816(accO[2*g+1], pah[kt], bh1);
                mma16816(accO[2*g+1], pah[kt], bl1);
                mma16816(accO[2*g+1], pal[kt], bh1);
            }
        }
    }

    // ---- epilogue: normalize, split-write Oa [B,T,H,D] as bf16 h/l ----
    float inv0 = 1.0f / l0r, inv1 = 1.0f / l1r;
    int gr0 = q0 + wq + (lane >> 2);
    #pragma unroll
    for (int nt = 0; nt < 16; nt++) {
        int d = nt * 8 + (lane & 3) * 2;
        uint32_t h0, e0, h1, e1;
        pack_split(accO[nt][0] * inv0, accO[nt][1] * inv0, h0, e0);
        pack_split(accO[nt][2] * inv1, accO[nt][3] * inv1, h1, e1);
        size_t o0 = (((size_t)(b*TT + gr0)     * NH) + h) * HD + d;
        size_t o1 = (((size_t)(b*TT + gr0 + 8) * NH) + h) * HD + d;
        *(uint32_t*)(Oah + o0) = h0;
        *(uint32_t*)(Oal + o0) = e0;
        *(uint32_t*)(Oah + o1) = h1;
        *(uint32_t*)(Oal + o1) = e1;
    }
}

// ============================ launch ========================================
extern "C" void kernel_launch(void* const* d_in, const int* in_sizes, int n_in,
                              void* d_out, int out_size)
{
    const float* x  = (const float*)d_in[0];
    const float* Wq = (const float*)d_in[1];
    const float* bq = (const float*)d_in[2];
    const float* Wk = (const float*)d_in[3];
    const float* bk = (const float*)d_in[4];
    const float* Wv = (const float*)d_in[5];
    const float* bv = (const float*)d_in[6];
    const float* Wo = (const float*)d_in[7];
    const float* bo = (const float*)d_in[8];
    float* out = (float*)d_out;

    __nv_bfloat16 *xh, *xl, *qh, *ql, *kh, *kl, *vh, *vl, *oah, *oal;
    __nv_bfloat16 *wqh, *wql, *wkh, *wkl, *wvh, *wvl, *woh, *wol;
    cudaGetSymbolAddress((void**)&xh,  g_xh);  cudaGetSymbolAddress((void**)&xl,  g_xl);
    cudaGetSymbolAddress((void**)&qh,  g_qh);  cudaGetSymbolAddress((void**)&ql,  g_ql);
    cudaGetSymbolAddress((void**)&kh,  g_kh);  cudaGetSymbolAddress((void**)&kl,  g_kl);
    cudaGetSymbolAddress((void**)&vh,  g_vh);  cudaGetSymbolAddress((void**)&vl,  g_vl);
    cudaGetSymbolAddress((void**)&oah, g_oah); cudaGetSymbolAddress((void**)&oal, g_oal);
    cudaGetSymbolAddress((void**)&wqh, g_wqh); cudaGetSymbolAddress((void**)&wql, g_wql);
    cudaGetSymbolAddress((void**)&wkh, g_wkh); cudaGetSymbolAddress((void**)&wkl, g_wkl);
    cudaGetSymbolAddress((void**)&wvh, g_wvh); cudaGetSymbolAddress((void**)&wvl, g_wvl);
    cudaGetSymbolAddress((void**)&woh, g_woh); cudaGetSymbolAddress((void**)&wol, g_wol);

    cudaFuncSetAttribute(gemm_mma_kernel, cudaFuncAttributeMaxDynamicSharedMemorySize,
                         GEMM_SMEM_BYTES);
    cudaFuncSetAttribute(attn_mma_kernel, cudaFuncAttributeMaxDynamicSharedMemorySize,
                         ATTN_SMEM_BYTES);

    // 1) split x
    {
        int n4 = (MROWS * KDIM) / 4;
        split_kernel<<<(n4 + 255) / 256, 256>>>(x, xh, xl, n4);
    }
    // 2) transpose + split weights: W[K][N] -> [N][K]
    transpose_split_kernel<<<dim3(2048/32, KDIM/32), dim3(32, 8)>>>(Wq, wqh, wql, KDIM, 2048);
    transpose_split_kernel<<<dim3(256/32,  KDIM/32), dim3(32, 8)>>>(Wk, wkh, wkl, KDIM, 256);
    transpose_split_kernel<<<dim3(256/32,  KDIM/32), dim3(32, 8)>>>(Wv, wvh, wvl, KDIM, 256);
    transpose_split_kernel<<<dim3(2048/32, KDIM/32), dim3(32, 8)>>>(Wo, woh, wol, KDIM, 2048);

    // 3) projections on HMMA; epilogue writes split bf16 directly
    gemm_mma_kernel<<<dim3(2048/128, MROWS/128), 256, GEMM_SMEM_BYTES>>>(
        xh, xl, wqh, wql, bq, nullptr, qh, ql, MROWS, 2048, KDIM);
    gemm_mma_kernel<<<dim3(256/128,  MROWS/128), 256, GEMM_SMEM_BYTES>>>(
        xh, xl, wkh, wkl, bk, nullptr, kh, kl, MROWS, 256, KDIM);
    gemm_mma_kernel<<<dim3(256/128,  MROWS/128), 256, GEMM_SMEM_BYTES>>>(
        xh, xl, wvh, wvl, bv, nullptr, vh, vl, MROWS, 256, KDIM);

    // 4) attention on HMMA; epilogue writes split bf16 directly
    attn_mma_kernel<<<dim3(TT/128, BB*NH), 256, ATTN_SMEM_BYTES>>>(
        qh, ql, kh, kl, vh, vl, oah, oal);

    // 5) output projection -> fp32 out
    gemm_mma_kernel<<<dim3(2048/128, MROWS/128), 256, GEMM_SMEM_BYTES>>>(
        oah, oal, woh, wol, bo, out, nullptr, nullptr, MROWS, 2048, KDIM);
}

// round 13
// speedup vs baseline: 1.0141x; 1.0017x over previous
#include <cuda_runtime.h>
#include <cuda_bf16.h>
#include <cstdint>
#include <math.h>

// Problem constants
#define BB   2
#define TT   2048
#define DIMC 2048
#define NH   16
#define NHK  2
#define HG   8
#define HD   128
#define MROWS (BB*TT)   // 4096
#define KDIM 2048

// ---------------- scratch (device globals) ----------------------------------
__device__ __nv_bfloat16 g_xh [(size_t)MROWS * KDIM];
__device__ __nv_bfloat16 g_xl [(size_t)MROWS * KDIM];
__device__ __nv_bfloat16 g_qh [(size_t)MROWS * NH  * HD];
__device__ __nv_bfloat16 g_ql [(size_t)MROWS * NH  * HD];
__device__ __nv_bfloat16 g_kh [(size_t)MROWS * NHK * HD];
__device__ __nv_bfloat16 g_kl [(size_t)MROWS * NHK * HD];
__device__ __nv_bfloat16 g_vh [(size_t)MROWS * NHK * HD];
__device__ __nv_bfloat16 g_vl [(size_t)MROWS * NHK * HD];
__device__ __nv_bfloat16 g_oah[(size_t)MROWS * KDIM];
__device__ __nv_bfloat16 g_oal[(size_t)MROWS * KDIM];
__device__ __nv_bfloat16 g_wqh[(size_t)2048 * KDIM];
__device__ __nv_bfloat16 g_wql[(size_t)2048 * KDIM];
__device__ __nv_bfloat16 g_wkh[(size_t)256  * KDIM];
__device__ __nv_bfloat16 g_wkl[(size_t)256  * KDIM];
__device__ __nv_bfloat16 g_wvh[(size_t)256  * KDIM];
__device__ __nv_bfloat16 g_wvl[(size_t)256  * KDIM];
__device__ __nv_bfloat16 g_woh[(size_t)2048 * KDIM];
__device__ __nv_bfloat16 g_wol[(size_t)2048 * KDIM];

// ===================== helpers ==============================================
__device__ __forceinline__ uint32_t smem_u32(const void* p) {
    uint32_t a;
    asm("{ .reg .u64 t; cvta.to.shared.u64 t, %1; cvt.u32.u64 %0, t; }" : "=r"(a) : "l"(p));
    return a;
}
__device__ __forceinline__ void ldm_x4(uint32_t addr, uint32_t& r0, uint32_t& r1,
                                       uint32_t& r2, uint32_t& r3) {
    asm volatile("ldmatrix.sync.aligned.m8n8.x4.shared.b16 {%0,%1,%2,%3}, [%4];"
                 : "=r"(r0), "=r"(r1), "=r"(r2), "=r"(r3) : "r"(addr));
}
__device__ __forceinline__ void ldm_x4_t(uint32_t addr, uint32_t& r0, uint32_t& r1,
                                         uint32_t& r2, uint32_t& r3) {
    asm volatile("ldmatrix.sync.aligned.m8n8.x4.trans.shared.b16 {%0,%1,%2,%3}, [%4];"
                 : "=r"(r0), "=r"(r1), "=r"(r2), "=r"(r3) : "r"(addr));
}
__device__ __forceinline__ void mma16816(float* d, const uint32_t* a, const uint32_t* b) {
    asm volatile("mma.sync.aligned.m16n8k16.row.col.f32.bf16.bf16.f32 "
                 "{%0,%1,%2,%3}, {%4,%5,%6,%7}, {%8,%9}, {%0,%1,%2,%3};"
                 : "+f"(d[0]), "+f"(d[1]), "+f"(d[2]), "+f"(d[3])
                 : "r"(a[0]), "r"(a[1]), "r"(a[2]), "r"(a[3]), "r"(b[0]), "r"(b[1]));
}
// split (x,y) fp32 pair into packed bf16x2 hi + lo
__device__ __forceinline__ void pack_split(float x, float y, uint32_t& h, uint32_t& l) {
    __nv_bfloat16 hx = __float2bfloat16(x), hy = __float2bfloat16(y);
    __nv_bfloat16 lx = __float2bfloat16(x - __bfloat162float(hx));
    __nv_bfloat16 ly = __float2bfloat16(y - __bfloat162float(hy));
    __nv_bfloat162 hp(hx, hy), lp(lx, ly);
    h = *(uint32_t*)&hp; l = *(uint32_t*)&lp;
}

// ===================== preprocessing ========================================
__global__ void split_kernel(const float* __restrict__ x,
                             __nv_bfloat16* __restrict__ h,
                             __nv_bfloat16* __restrict__ l, int n4)
{
    int i = blockIdx.x * blockDim.x + threadIdx.x;
    if (i >= n4) return;
    float4 v = *(const float4*)(x + (size_t)i * 4);
    __nv_bfloat16 h0 = __float2bfloat16(v.x), h1 = __float2bfloat16(v.y);
    __nv_bfloat16 h2 = __float2bfloat16(v.z), h3 = __float2bfloat16(v.w);
    __nv_bfloat16 l0 = __float2bfloat16(v.x - __bfloat162float(h0));
    __nv_bfloat16 l1 = __float2bfloat16(v.y - __bfloat162float(h1));
    __nv_bfloat16 l2 = __float2bfloat16(v.z - __bfloat162float(h2));
    __nv_bfloat16 l3 = __float2bfloat16(v.w - __bfloat162float(h3));
    __nv_bfloat162* hp = (__nv_bfloat162*)(h + (size_t)i * 4);
    __nv_bfloat162* lp = (__nv_bfloat162*)(l + (size_t)i * 4);
    hp[0] = __nv_bfloat162(h0, h1); hp[1] = __nv_bfloat162(h2, h3);
    lp[0] = __nv_bfloat162(l0, l1); lp[1] = __nv_bfloat162(l2, l3);
}

__global__ void transpose_split_kernel(const float* __restrict__ W,
                                       __nv_bfloat16* __restrict__ Th,
                                       __nv_bfloat16* __restrict__ Tl,
                                       int Kd, int Nd)
{
    __shared__ float t[32][33];
    int bx = blockIdx.x * 32;
    int by = blockIdx.y * 32;
    int tx = threadIdx.x, ty = threadIdx.y;
    #pragma unroll
    for (int i = 0; i < 32; i += 8)
        t[ty + i][tx] = W[(size_t)(by + ty + i) * Nd + bx + tx];
    __syncthreads();
    #pragma unroll
    for (int i = 0; i < 32; i += 8) {
        float v = t[tx][ty + i];
        __nv_bfloat16 hv = __float2bfloat16(v);
        __nv_bfloat16 lv = __float2bfloat16(v - __bfloat162float(hv));
        size_t o = (size_t)(bx + ty + i) * Kd + by + tx;
        Th[o] = hv;
        Tl[o] = lv;
    }
}

// ===================== HMMA split-bf16 GEMM =================================
// C = (Ah+Al)[M,K] @ (Bh+Bl)[N,K]^T + bias.
// If Cl != null: write split bf16 (Ch,Cl). Else write fp32 C.
#define GS       72
#define TILE_E   (128 * GS)
#define SA_H     0
#define SA_L     (TILE_E * 2)
#define SB_H     (TILE_E * 4)
#define SB_L     (TILE_E * 6)
#define GEMM_SMEM_BYTES (TILE_E * 8)

__global__ __launch_bounds__(256, 1)
void gemm_mma_kernel(const __nv_bfloat16* __restrict__ Ah,
                     const __nv_bfloat16* __restrict__ Al,
                     const __nv_bfloat16* __restrict__ Bh,
                     const __nv_bfloat16* __restrict__ Bl,
                     const float* __restrict__ bias,
                     float* __restrict__ C,
                     __nv_bfloat16* __restrict__ Ch,
                     __nv_bfloat16* __restrict__ Cl,
                     int M, int N, int K)
{
    extern __shared__ char smem[];
    const uint32_t sb = smem_u32(smem);

    const int tid  = threadIdx.x;
    const int wid  = tid >> 5;
    const int lane = tid & 31;
    const int n0 = blockIdx.x * 128;
    const int m0 = blockIdx.y * 128;
    const int wm = (wid >> 2) * 64;
    const int wn = (wid & 3) * 32;

    float acc[4][4][4];
    #pragma unroll
    for (int i = 0; i < 4; i++)
        #pragma unroll
        for (int j = 0; j < 4; j++)
            #pragma unroll
            for (int q = 0; q < 4; q++) acc[i][j][q] = 0.f;

    const int a_row = wm + (lane & 15);
    const int a_kof = (lane >> 4) * 8;
    const int b_row = wn + (lane & 7) + ((lane >> 4) << 3);
    const int b_kof = ((lane >> 3) & 1) * 8;

    for (int k0 = 0; k0 < K; k0 += 64) {
        #pragma unroll
        for (int i = 0; i < 4; i++) {
            int idx = tid + i * 256;
            int r   = idx >> 3;
            int c8  = idx & 7;
            uint32_t so = (uint32_t)(r * GS + c8 * 8) * 2;
            size_t ga = (size_t)(m0 + r) * K + k0 + c8 * 8;
            size_t gb = (size_t)(n0 + r) * K + k0 + c8 * 8;
            *(uint4*)(smem + SA_H + so) = *(const uint4*)(Ah + ga);
            *(uint4*)(smem + SA_L + so) = *(const uint4*)(Al + ga);
            *(uint4*)(smem + SB_H + so) = *(const uint4*)(Bh + gb);
            *(uint4*)(smem + SB_L + so) = *(const uint4*)(Bl + gb);
        }
        __syncthreads();

        #pragma unroll
        for (int ks = 0; ks < 4; ks++) {
            const int kk = ks * 16;
            uint32_t ah[4][4], al[4][4], bh[4][2], bl[4][2];

            #pragma unroll
            for (int mi = 0; mi < 4; mi++) {
                uint32_t off = (uint32_t)((a_row + mi * 16) * GS + kk + a_kof) * 2;
                ldm_x4(sb + SA_H + off, ah[mi][0], ah[mi][1], ah[mi][2], ah[mi][3]);
                ldm_x4(sb + SA_L + off, al[mi][0], al[mi][1], al[mi][2], al[mi][3]);
            }
            #pragma unroll
            for (int p = 0; p < 2; p++) {
                uint32_t off = (uint32_t)((b_row + p * 16) * GS + kk + b_kof) * 2;
                ldm_x4(sb + SB_H + off, bh[2*p][0], bh[2*p][1], bh[2*p+1][0], bh[2*p+1][1]);
                ldm_x4(sb + SB_L + off, bl[2*p][0], bl[2*p][1], bl[2*p+1][0], bl[2*p+1][1]);
            }
            #pragma unroll
            for (int mi = 0; mi < 4; mi++)
                #pragma unroll
                for (int nj = 0; nj < 4; nj++) {
                    mma16816(acc[mi][nj], ah[mi], bh[nj]);
                    mma16816(acc[mi][nj], ah[mi], bl[nj]);
                    mma16816(acc[mi][nj], al[mi], bh[nj]);
                }
        }
        __syncthreads();
    }

    const int r_base = m0 + wm + (lane >> 2);
    const int c_base = n0 + wn + (lane & 3) * 2;
    #pragma unroll
    for (int mi = 0; mi < 4; mi++) {
        #pragma unroll
        for (int nj = 0; nj < 4; nj++) {
            int cc = c_base + nj * 8;
            float b0 = bias[cc], b1 = bias[cc + 1];
            int r0 = r_base + mi * 16;
            float v00 = acc[mi][nj][0] + b0, v01 = acc[mi][nj][1] + b1;
            float v10 = acc[mi][nj][2] + b0, v11 = acc[mi][nj][3] + b1;
            if (Cl) {
                uint32_t h0, l0, h1, l1;
                pack_split(v00, v01, h0, l0);
                pack_split(v10, v11, h1, l1);
                *(uint32_t*)(Ch + (size_t)r0 * N + cc)       = h0;
                *(uint32_t*)(Cl + (size_t)r0 * N + cc)       = l0;
                *(uint32_t*)(Ch + (size_t)(r0 + 8) * N + cc) = h1;
                *(uint32_t*)(Cl + (size_t)(r0 + 8) * N + cc) = l1;
            } else {
                *(float2*)(C + (size_t)r0 * N + cc)       = make_float2(v00, v01);
                *(float2*)(C + (size_t)(r0 + 8) * N + cc) = make_float2(v10, v11);
            }
        }
    }
}

// ======================= HMMA flash attention ================================
// Block: 128 q-rows of one (b,h); 8 warps x 16 q-rows. kv tiles of 64.
// smem (bf16, stride 136): Qh/Ql 128x136, Kh/Kl/Vh/Vl 64x136.
#define QS 136
#define OQ_H 0
#define OQ_L (128*QS*2)
#define OK_H (OQ_L + 128*QS*2)
#define OK_L (OK_H + 64*QS*2)
#define OV_H (OK_L + 64*QS*2)
#define OV_L (OV_H + 64*QS*2)
#define ATTN_SMEM_BYTES (OV_L + 64*QS*2)   // 139264

__global__ __launch_bounds__(256, 1)
void attn_mma_kernel(const __nv_bfloat16* __restrict__ Qh,
                     const __nv_bfloat16* __restrict__ Ql,
                     const __nv_bfloat16* __restrict__ Kh,
                     const __nv_bfloat16* __restrict__ Kl,
                     const __nv_bfloat16* __restrict__ Vh,
                     const __nv_bfloat16* __restrict__ Vl,
                     __nv_bfloat16* __restrict__ Oah,
                     __nv_bfloat16* __restrict__ Oal)
{
    extern __shared__ char smem[];
    const uint32_t sb = smem_u32(smem);

    const int tid  = threadIdx.x;
    const int wid  = tid >> 5;
    const int lane = tid & 31;
    const int q0 = blockIdx.x * 128;
    const int b  = blockIdx.y >> 4;
    const int h  = blockIdx.y & 15;
    const int hk = h >> 3;
    const int wq = wid * 16;

    // ---- load Q tile (128 x 128, h+l) ----
    for (int idx = tid; idx < 128 * 16; idx += 256) {
        int r  = idx >> 4;
        int c8 = idx & 15;
        uint32_t so = (uint32_t)(r * QS + c8 * 8) * 2;
        size_t g = (((size_t)(b*TT + q0 + r) * NH) + h) * HD + c8 * 8;
        *(uint4*)(smem + OQ_H + so) = *(const uint4*)(Qh + g);
        *(uint4*)(smem + OQ_L + so) = *(const uint4*)(Ql + g);
    }

    const int a_row  = wq + (lane & 15);
    const int a_kof  = (lane >> 4) * 8;
    const int kb_row = (lane & 7) + ((lane >> 4) << 3);
    const int kb_kof = ((lane >> 3) & 1) * 8;
    const int v_row  = lane & 15;
    const int v_col  = (lane >> 4) * 8;

    float accO[16][4];
    #pragma unroll
    for (int i = 0; i < 16; i++)
        #pragma unroll
        for (int q = 0; q < 4; q++) accO[i][q] = 0.f;
    float m0r = -1e30f, m1r = -1e30f, l0r = 0.f, l1r = 0.f;
    const float scale = 0.08838834764831845f;

    for (int j0 = 0; j0 < TT; j0 += 64) {
        __syncthreads();   // previous-iter smem reads done (also covers Q store, 1st iter)
        // ---- load K,V tile (64 x 128, h+l each) ----
        for (int idx = tid; idx < 64 * 16; idx += 256) {
            int r  = idx >> 4;
            int c8 = idx & 15;
            uint32_t so = (uint32_t)(r * QS + c8 * 8) * 2;
            size_t g = (((size_t)(b*TT + j0 + r) * NHK) + hk) * HD + c8 * 8;
            *(uint4*)(smem + OK_H + so) = *(const uint4*)(Kh + g);
            *(uint4*)(smem + OK_L + so) = *(const uint4*)(Kl + g);
            *(uint4*)(smem + OV_H + so) = *(const uint4*)(Vh + g);
            *(uint4*)(smem + OV_L + so) = *(const uint4*)(Vl + g);
        }
        __syncthreads();

        // ---- S = Q K^T (3 split terms) ----
        float s[8][4];
        #pragma unroll
        for (int t = 0; t < 8; t++)
            #pragma unroll
            for (int q = 0; q < 4; q++) s[t][q] = 0.f;

        #pragma unroll
        for (int ks = 0; ks < 8; ks++) {
            const int kk = ks * 16;
            uint32_t qfh[4], qfl[4];
            uint32_t qoff = (uint32_t)(a_row * QS + kk + a_kof) * 2;
            ldm_x4(sb + OQ_H + qoff, qfh[0], qfh[1], qfh[2], qfh[3]);
            ldm_x4(sb + OQ_L + qoff, qfl[0], qfl[1], qfl[2], qfl[3]);
            #pragma unroll
            for (int g = 0; g < 4; g++) {
                uint32_t koff = (uint32_t)((g*16 + kb_row) * QS + kk + kb_kof) * 2;
                uint32_t h0,h1,h2,h3, e0,e1,e2,e3;
                ldm_x4(sb + OK_H + koff, h0, h1, h2, h3);
                ldm_x4(sb + OK_L + koff, e0, e1, e2, e3);
                uint32_t bh0[2] = {h0, h1}, bh1[2] = {h2, h3};
                uint32_t bl0[2] = {e0, e1}, bl1[2] = {e2, e3};
                mma16816(s[2*g],   qfh, bh0);
                mma16816(s[2*g],   qfh, bl0);
                mma16816(s[2*g],   qfl, bh0);
                mma16816(s[2*g+1], qfh, bh1);
                mma16816(s[2*g+1], qfh, bl1);
                mma16816(s[2*g+1], qfl, bh1);
            }
        }

        // ---- online softmax (rows: lane>>2 and +8) ----
        float ml0 = -1e30f, ml1 = -1e30f;
        #pragma unroll
        for (int t = 0; t < 8; t++) {
            #pragma unroll
            for (int q = 0; q < 4; q++) {
                float sv = fminf(fmaxf(s[t][q] * scale, -100.f), 100.f);
                s[t][q] = sv;
                if (q < 2) ml0 = fmaxf(ml0, sv); else ml1 = fmaxf(ml1, sv);
            }
        }
        ml0 = fmaxf(ml0, __shfl_xor_sync(0xffffffffu, ml0, 1));
        ml0 = fmaxf(ml0, __shfl_xor_sync(0xffffffffu, ml0, 2));
        ml1 = fmaxf(ml1, __shfl_xor_sync(0xffffffffu, ml1, 1));
        ml1 = fmaxf(ml1, __shfl_xor_sync(0xffffffffu, ml1, 2));
        float mn0 = fmaxf(m0r, ml0), mn1 = fmaxf(m1r, ml1);
        float c0 = __expf(m0r - mn0), c1 = __expf(m1r - mn1);
        float ls0 = 0.f, ls1 = 0.f;
        #pragma unroll
        for (int t = 0; t < 8; t++) {
            float p0 = __expf(s[t][0] - mn0);
            float p1 = __expf(s[t][1] - mn0);
            float p2 = __expf(s[t][2] - mn1);
            float p3 = __expf(s[t][3] - mn1);
            s[t][0] = p0; s[t][1] = p1; s[t][2] = p2; s[t][3] = p3;
            ls0 += p0 + p1; ls1 += p2 + p3;
        }
        ls0 += __shfl_xor_sync(0xffffffffu, ls0, 1);
        ls0 += __shfl_xor_sync(0xffffffffu, ls0, 2);
        ls1 += __shfl_xor_sync(0xffffffffu, ls1, 1);
        ls1 += __shfl_xor_sync(0xffffffffu, ls1, 2);
        l0r = l0r * c0 + ls0; m0r = mn0;
        l1r = l1r * c1 + ls1; m1r = mn1;
        #pragma unroll
        for (int nt = 0; nt < 16; nt++) {
            accO[nt][0] *= c0; accO[nt][1] *= c0;
            accO[nt][2] *= c1; accO[nt][3] *= c1;
        }

        // ---- pack P into split A-fragments (in-register) ----
        uint32_t pah[4][4], pal[4][4];
        #pragma unroll
        for (int kt = 0; kt < 4; kt++) {
            int t0 = 2*kt, t1 = t0 + 1;
            pack_split(s[t0][0], s[t0][1], pah[kt][0], pal[kt][0]);
            pack_split(s[t0][2], s[t0][3], pah[kt][1], pal[kt][1]);
            pack_split(s[t1][0], s[t1][1], pah[kt][2], pal[kt][2]);
            pack_split(s[t1][2], s[t1][3], pah[kt][3], pal[kt][3]);
        }

        // ---- O += P V (3 split terms) ----
        #pragma unroll
        for (int kt = 0; kt < 4; kt++) {
            #pragma unroll
            for (int g = 0; g < 8; g++) {
                uint32_t voff = (uint32_t)((kt*16 + v_row) * QS + g*16 + v_col) * 2;
                uint32_t h0,h1,h2,h3, e0,e1,e2,e3;
                ldm_x4_t(sb + OV_H + voff, h0, h1, h2, h3);
                ldm_x4_t(sb + OV_L + voff, e0, e1, e2, e3);
                uint32_t bh0[2] = {h0, h1}, bh1[2] = {h2, h3};
                uint32_t bl0[2] = {e0, e1}, bl1[2] = {e2, e3};
                mma16816(accO[2*g],   pah[kt], bh0);
                mma16816(accO[2*g],   pah[kt], bl0);
                mma16816(accO[2*g],   pal[kt], bh0);
                mma16816(accO[2*g+1], pah[kt], bh1);
                mma16816(accO[2*g+1], pah[kt], bl1);
                mma16816(accO[2*g+1], pal[kt], bh1);
            }
        }
    }

    // ---- epilogue: normalize, split-write Oa [B,T,H,D] as bf16 h/l ----
    float inv0 = 1.0f / l0r, inv1 = 1.0f / l1r;
    int gr0 = q0 + wq + (lane >> 2);
    #pragma unroll
    for (int nt = 0; nt < 16; nt++) {
        int d = nt * 8 + (lane & 3) * 2;
        uint32_t h0, e0, h1, e1;
        pack_split(accO[nt][0] * inv0, accO[nt][1] * inv0, h0, e0);
        pack_split(accO[nt][2] * inv1, accO[nt][3] * inv1, h1, e1);
        size_t o0 = (((size_t)(b*TT + gr0)     * NH) + h) * HD + d;
        size_t o1 = (((size_t)(b*TT + gr0 + 8) * NH) + h) * HD + d;
        *(uint32_t*)(Oah + o0) = h0;
        *(uint32_t*)(Oal + o0) = e0;
        *(uint32_t*)(Oah + o1) = h1;
        *(uint32_t*)(Oal + o1) = e1;
    }
}

// ============================ launch ========================================
extern "C" void kernel_launch(void* const* d_in, const int* in_sizes, int n_in,
                              void* d_out, int out_size)
{
    const float* x  = (const float*)d_in[0];
    const float* Wq = (const float*)d_in[1];
    const float* bq = (const float*)d_in[2];
    const float* Wk = (const float*)d_in[3];
    const float* bk = (const float*)d_in[4];
    const float* Wv = (const float*)d_in[5];
    const float* bv = (const float*)d_in[6];
    const float* Wo = (const float*)d_in[7];
    const float* bo = (const float*)d_in[8];
    float* out = (float*)d_out;

    __nv_bfloat16 *xh, *xl, *qh, *ql, *kh, *kl, *vh, *vl, *oah, *oal;
    __nv_bfloat16 *wqh, *wql, *wkh, *wkl, *wvh, *wvl, *woh, *wol;
    cudaGetSymbolAddress((void**)&xh,  g_xh);  cudaGetSymbolAddress((void**)&xl,  g_xl);
    cudaGetSymbolAddress((void**)&qh,  g_qh);  cudaGetSymbolAddress((void**)&ql,  g_ql);
    cudaGetSymbolAddress((void**)&kh,  g_kh);  cudaGetSymbolAddress((void**)&kl,  g_kl);
    cudaGetSymbolAddress((void**)&vh,  g_vh);  cudaGetSymbolAddress((void**)&vl,  g_vl);
    cudaGetSymbolAddress((void**)&oah, g_oah); cudaGetSymbolAddress((void**)&oal, g_oal);
    cudaGetSymbolAddress((void**)&wqh, g_wqh); cudaGetSymbolAddress((void**)&wql, g_wql);
    cudaGetSymbolAddress((void**)&wkh, g_wkh); cudaGetSymbolAddress((void**)&wkl, g_wkl);
    cudaGetSymbolAddress((void**)&wvh, g_wvh); cudaGetSymbolAddress((void**)&wvl, g_wvl);
    cudaGetSymbolAddress((void**)&woh, g_woh); cudaGetSymbolAddress((void**)&wol, g_wol);

    cudaFuncSetAttribute(gemm_mma_kernel, cudaFuncAttributeMaxDynamicSharedMemorySize,
                         GEMM_SMEM_BYTES);
    cudaFuncSetAttribute(attn_mma_kernel, cudaFuncAttributeMaxDynamicSharedMemorySize,
                         ATTN_SMEM_BYTES);

    // 1) split x
    {
        int n4 = (MROWS * KDIM) / 4;
        split_kernel<<<(n4 + 255) / 256, 256>>>(x, xh, xl, n4);
    }
    // 2) transpose + split weights: W[K][N] -> [N][K]
    transpose_split_kernel<<<dim3(2048/32, KDIM/32), dim3(32, 8)>>>(Wq, wqh, wql, KDIM, 2048);
    transpose_split_kernel<<<dim3(256/32,  KDIM/32), dim3(32, 8)>>>(Wk, wkh, wkl, KDIM, 256);
    transpose_split_kernel<<<dim3(256/32,  KDIM/32), dim3(32, 8)>>>(Wv, wvh, wvl, KDIM, 256);
    transpose_split_kernel<<<dim3(2048/32, KDIM/32), dim3(32, 8)>>>(Wo, woh, wol, KDIM, 2048);

    // 3) projections on HMMA; epilogue writes split bf16 directly
    gemm_mma_kernel<<<dim3(2048/128, MROWS/128), 256, GEMM_SMEM_BYTES>>>(
        xh, xl, wqh, wql, bq, nullptr, qh, ql, MROWS, 2048, KDIM);
    gemm_mma_kernel<<<dim3(256/128,  MROWS/128), 256, GEMM_SMEM_BYTES>>>(
        xh, xl, wkh, wkl, bk, nullptr, kh, kl, MROWS, 256, KDIM);
    gemm_mma_kernel<<<dim3(256/128,  MROWS/128), 256, GEMM_SMEM_BYTES>>>(
        xh, xl, wvh, wvl, bv, nullptr, vh, vl, MROWS, 256, KDIM);

    // 4) attention on HMMA; epilogue writes split bf16 directly
    attn_mma_kernel<<<dim3(TT/128, BB*NH), 256, ATTN_SMEM_BYTES>>>(
        qh, ql, kh, kl, vh, vl, oah, oal);

    // 5) output projection -> fp32 out
    gemm_mma_kernel<<<dim3(2048/128, MROWS/128), 256, GEMM_SMEM_BYTES>>>(
        oah, oal, woh, wol, bo, out, nullptr, nullptr, MROWS, 2048, KDIM);
}